// round 2
// baseline (speedup 1.0000x reference)
#include <cuda_runtime.h>
#include <math.h>

// Problem constants
// B=8, CI=CO=64, H=W=256, M1=M2=16, G=4, NEXP=15, RANK=4, SCALING=0.1
#define NTOT (8*64*256*256)

// ---------------- scratch (device globals; no allocation allowed) ----------------
__device__ float  d_FW [256*128];       // forward W-DFT matrix  [w][2*ky + re/im]
__device__ float2 d_FH [128*256];       // forward H-DFT matrix  [kxIdx][h]
__device__ float2 d_FHI[256*128];       // inverse H matrix      [h][kxIdx]
__device__ float  d_FIW[128*256];       // inverse W matrix      [2*ky+c][w]  (1/(H*W) folded)
__device__ float  d_A  [512*256*128];   // stage1 out: [bc][h][2*ky+c]
__device__ float2 d_Xf [512*128*64];    // x_ft corners [bc][kxIdx][ky]
__device__ float2 d_Of [512*128*64];    // out_ft corners [bo][kxIdx][ky]
__device__ float  d_Z  [512*256*128];   // stage5 out: [bo][h][2*ky+c]
__device__ float2 d_wt [2*256*64*64];   // transposed base weights [t][p][i][o]
__device__ float2 d_lbt[2*15*256*4*64]; // transposed lora_b [t][e][p][r][o]
__device__ float2 d_la [2*15*4*64];     // lora_a complex [t][e][r][i]
__device__ float  d_gate[30];           // sigmoid(gate) [t*15+e]

// ---------------- packed fp32x2 helpers (FFMA2 — PTX-only on sm_103a) ----------------
#define FMAX2(acc, a, b) \
    asm("fma.rn.f32x2 %0, %1, %2, %0;" : "+l"(acc) : "l"(a), "l"(b))
#define PACK2(d, x, y) \
    asm("mov.b64 %0, {%1, %2};" : "=l"(d) : "f"(x), "f"(y))

__device__ __forceinline__ void cfma(float2& c, float2 a, float2 b) {
    c.x = fmaf(a.x, b.x, c.x); c.x = fmaf(-a.y, b.y, c.x);
    c.y = fmaf(a.x, b.y, c.y); c.y = fmaf( a.y, b.x, c.y);
}

// ---------------- init: trig tables (index reduced mod 256 -> exact periodicity) ------
__global__ void init_tables_k() {
    int id = blockIdx.x * 256 + threadIdx.x;
    const float STEP = 6.283185307179586f / 256.0f;
    if (id < 32768) {                       // FW
        int w = id >> 7, n = id & 127, ky = n >> 1;
        float ang = STEP * (float)((w * ky) & 255);
        d_FW[id] = (n & 1) ? -sinf(ang) : cosf(ang);
    } else if (id < 65536) {                // FH
        int r = id - 32768; int kxi = r >> 8, h = r & 255;
        int kx = (kxi < 64) ? kxi : kxi + 128;
        float ang = STEP * (float)((kx * h) & 255);
        d_FH[r] = make_float2(cosf(ang), -sinf(ang));
    } else if (id < 98304) {                // FHI
        int r = id - 65536; int h = r >> 7, kxi = r & 127;
        int kx = (kxi < 64) ? kxi : kxi + 128;
        float ang = STEP * (float)((kx * h) & 255);
        d_FHI[r] = make_float2(cosf(ang), sinf(ang));
    } else if (id < 131072) {               // FIW (1/65536 folded, Im(ky=0) row -> sin(0)=0)
        int r = id - 98304; int n = r >> 8, w = r & 255, k = n >> 1;
        float s = ((k == 0) ? 1.0f : 2.0f) * (1.0f / 65536.0f);
        float ang = STEP * (float)((k * w) & 255);
        d_FIW[r] = (n & 1) ? -s * sinf(ang) : s * cosf(ang);
    }
}

__global__ void init_wt_k(const float* __restrict__ w1re, const float* __restrict__ w1im,
                          const float* __restrict__ w2re, const float* __restrict__ w2im) {
    int id = blockIdx.x * 256 + threadIdx.x;
    if (id >= 2 * 256 * 4096) return;
    int t = id >> 20, rem = id & 1048575;
    int p = rem >> 12, io = rem & 4095;
    int i = io >> 6, o = io & 63;
    const float* re = t ? w2re : w1re;
    const float* im = t ? w2im : w1im;
    size_t src = ((size_t)(i * 64 + o)) * 256 + p;
    d_wt[id] = make_float2(re[src], im[src]);
}

__global__ void init_lbt_k(const float* __restrict__ b1re, const float* __restrict__ b1im,
                           const float* __restrict__ b2re, const float* __restrict__ b2im) {
    int id = blockIdx.x * 256 + threadIdx.x;
    if (id >= 2 * 15 * 256 * 256) return;
    int t = id / 983040, rem = id % 983040;
    int e = rem >> 16, rem2 = rem & 65535;
    int p = rem2 >> 8, ro = rem2 & 255;
    int r = ro >> 6, o = ro & 63;
    const float* re = t ? b2re : b1re;
    const float* im = t ? b2im : b1im;
    size_t src = (((size_t)(e * 64 + o)) * 4 + r) * 256 + p;
    d_lbt[id] = make_float2(re[src], im[src]);
}

__global__ void init_small_k(const float* __restrict__ la1re, const float* __restrict__ la1im,
                             const float* __restrict__ la2re, const float* __restrict__ la2im,
                             const float* __restrict__ g1, const float* __restrict__ g2,
                             float* sp_out) {
    int tid = threadIdx.x;
    for (int id = tid; id < 7680; id += 256) {
        int t = id / 3840, rem = id % 3840;
        const float* re = t ? la2re : la1re;
        const float* im = t ? la2im : la1im;
        d_la[id] = make_float2(re[rem], im[rem]);
    }
    __shared__ float gs[30];
    if (tid < 30) {
        float v = (tid < 15) ? g1[tid] : g2[tid - 15];
        float s = 1.0f / (1.0f + expf(-v));
        d_gate[tid] = s;
        gs[tid] = s;
    }
    __syncthreads();
    if (tid == 0 && sp_out) {
        float s = 0.0f;
        for (int i = 0; i < 30; i++) s += gs[i];
        *sp_out = s / 15.0f;
    }
}

// ---------------- fp32 SGEMM, packed f32x2 inner loop ----------------
// BM=128, BN=128, BK=16, 256 threads, 8x8 micro-tile (stored as 8x4 f32x2 pairs).
__global__ __launch_bounds__(256) void sgemm_k(const float* __restrict__ Amat,
                                               const float* __restrict__ Bmat,
                                               float* __restrict__ Cmat,
                                               int Kdim, int Ncols) {
    __shared__ float As[16][128];
    __shared__ float Bs[16][128];
    int tid = threadIdx.x;
    int m0 = blockIdx.x * 128, n0 = blockIdx.y * 128;
    int tx = tid & 15, ty = tid >> 4;
    unsigned long long accp[8][4] = {};   // zero bits == {0.0f, 0.0f}
    for (int k0 = 0; k0 < Kdim; k0 += 16) {
#pragma unroll
        for (int l = 0; l < 2; l++) {
            int flat = tid + l * 256;
            int row = flat >> 2, c4 = (flat & 3) * 4;
            float4 v = *(const float4*)(Amat + (size_t)(m0 + row) * Kdim + k0 + c4);
            As[c4 + 0][row] = v.x; As[c4 + 1][row] = v.y;
            As[c4 + 2][row] = v.z; As[c4 + 3][row] = v.w;
        }
#pragma unroll
        for (int l = 0; l < 2; l++) {
            int flat = tid + l * 256;
            int row = flat >> 5, c4 = (flat & 31) * 4;
            *(float4*)(&Bs[row][c4]) = *(const float4*)(Bmat + (size_t)(k0 + row) * Ncols + n0 + c4);
        }
        __syncthreads();
#pragma unroll
        for (int k = 0; k < 16; k++) {
            float4 a0 = *(const float4*)(&As[k][ty * 4]);
            float4 a1 = *(const float4*)(&As[k][64 + ty * 4]);
            unsigned long long ap[8];
            PACK2(ap[0], a0.x, a0.x); PACK2(ap[1], a0.y, a0.y);
            PACK2(ap[2], a0.z, a0.z); PACK2(ap[3], a0.w, a0.w);
            PACK2(ap[4], a1.x, a1.x); PACK2(ap[5], a1.y, a1.y);
            PACK2(ap[6], a1.z, a1.z); PACK2(ap[7], a1.w, a1.w);
            unsigned long long bp[4];
            bp[0] = *(const unsigned long long*)(&Bs[k][tx * 4]);
            bp[1] = *(const unsigned long long*)(&Bs[k][tx * 4 + 2]);
            bp[2] = *(const unsigned long long*)(&Bs[k][64 + tx * 4]);
            bp[3] = *(const unsigned long long*)(&Bs[k][64 + tx * 4 + 2]);
#pragma unroll
            for (int i = 0; i < 8; i++)
#pragma unroll
                for (int j = 0; j < 4; j++)
                    FMAX2(accp[i][j], ap[i], bp[j]);
        }
        __syncthreads();
    }
#pragma unroll
    for (int i = 0; i < 8; i++) {
        int m = m0 + ((i < 4) ? (ty * 4 + i) : (64 + ty * 4 + (i - 4)));
        float2 p0 = *(float2*)(&accp[i][0]);
        float2 p1 = *(float2*)(&accp[i][1]);
        float2 p2 = *(float2*)(&accp[i][2]);
        float2 p3 = *(float2*)(&accp[i][3]);
        float4 v0 = {p0.x, p0.y, p1.x, p1.y};
        float4 v1 = {p2.x, p2.y, p3.x, p3.y};
        *(float4*)(Cmat + (size_t)m * Ncols + n0 + tx * 4)      = v0;
        *(float4*)(Cmat + (size_t)m * Ncols + n0 + 64 + tx * 4) = v1;
    }
}

// ---------------- batched complex GEMM, packed f32x2 inner loop ----------------
// C[bat][M,64] = F[M,K] (shared across batch) * Bm[bat][K,64]
// BM=64, BN=64, BK=16, 256 threads, 4x4 complex micro-tile.
// Complex MAC: acc{re,im} += {f.x,f.x}*{b.x,b.y} + {f.y,f.y}*{-b.y,b.x}
__global__ __launch_bounds__(256) void cgemm_k(const float2* __restrict__ F,
                                               const float2* __restrict__ Bm,
                                               float2* __restrict__ Cm,
                                               int Mdim, int Kdim) {
    int bat = blockIdx.x;
    int m0 = blockIdx.y * 64;
    const float2* Bb = Bm + (size_t)bat * Kdim * 64;
    float2* Cb = Cm + (size_t)bat * Mdim * 64;
    __shared__ float2 Fs[16][64];
    __shared__ float2 Bs[16][64];
    __shared__ float2 Bw[16][64];   // negated-swapped copy {-im, re}
    int tid = threadIdx.x;
    int tx = tid & 15, ty = tid >> 4;
    unsigned long long acc[4][4] = {};
    for (int k0 = 0; k0 < Kdim; k0 += 16) {
#pragma unroll
        for (int l = 0; l < 2; l++) {
            int flat = tid + l * 256;
            int row = flat >> 3, c = flat & 7;
            float4 v = *(const float4*)(F + (size_t)(m0 + row) * Kdim + k0 + c * 2);
            Fs[c * 2][row]     = make_float2(v.x, v.y);
            Fs[c * 2 + 1][row] = make_float2(v.z, v.w);
        }
#pragma unroll
        for (int l = 0; l < 2; l++) {
            int flat = tid + l * 256;
            int row = flat >> 5, c = flat & 31;
            float4 v = *(const float4*)(Bb + (size_t)(k0 + row) * 64 + c * 2);
            Bs[row][c * 2]     = make_float2(v.x, v.y);
            Bs[row][c * 2 + 1] = make_float2(v.z, v.w);
            Bw[row][c * 2]     = make_float2(-v.y, v.x);
            Bw[row][c * 2 + 1] = make_float2(-v.w, v.z);
        }
        __syncthreads();
#pragma unroll
        for (int k = 0; k < 16; k++) {
            float4 f01 = *(const float4*)(&Fs[k][ty * 4]);
            float4 f23 = *(const float4*)(&Fs[k][ty * 4 + 2]);
            unsigned long long fx[4], fy[4];
            PACK2(fx[0], f01.x, f01.x); PACK2(fy[0], f01.y, f01.y);
            PACK2(fx[1], f01.z, f01.z); PACK2(fy[1], f01.w, f01.w);
            PACK2(fx[2], f23.x, f23.x); PACK2(fy[2], f23.y, f23.y);
            PACK2(fx[3], f23.z, f23.z); PACK2(fy[3], f23.w, f23.w);
            unsigned long long bp[4], bw[4];
#pragma unroll
            for (int j = 0; j < 4; j++) {
                bp[j] = *(const unsigned long long*)(&Bs[k][tx * 4 + j]);
                bw[j] = *(const unsigned long long*)(&Bw[k][tx * 4 + j]);
            }
#pragma unroll
            for (int i = 0; i < 4; i++)
#pragma unroll
                for (int j = 0; j < 4; j++) {
                    FMAX2(acc[i][j], fx[i], bp[j]);
                    FMAX2(acc[i][j], fy[i], bw[j]);
                }
        }
        __syncthreads();
    }
#pragma unroll
    for (int i = 0; i < 4; i++) {
        int m = m0 + ty * 4 + i;
#pragma unroll
        for (int j = 0; j < 4; j += 2) {
            float2 p0 = *(float2*)(&acc[i][j]);
            float2 p1 = *(float2*)(&acc[i][j + 1]);
            float4 v = {p0.x, p0.y, p1.x, p1.y};
            *(float4*)(Cb + (size_t)m * 64 + tx * 4 + j) = v;
        }
    }
}

// ---------------- base tiles: Of[b,o,p] = sum_i Xf[b,i,p] * w[i,o,p] ----------------
__global__ __launch_bounds__(512) void base_mul_k() {
    int t = blockIdx.x;
    int p = blockIdx.y;
    int x = p >> 4, y = p & 15;
    int kxIdx = (t == 0) ? x : (112 + x);
    int ky = y;
    __shared__ float2 Xs[8][64];
    int tid = threadIdx.x;
    {
        int b = tid >> 6, i = tid & 63;
        Xs[b][i] = d_Xf[(size_t)(b * 64 + i) * 8192 + kxIdx * 64 + ky];
    }
    __syncthreads();
    int o = tid & 63, b = tid >> 6;
    const float2* wp = d_wt + ((size_t)t * 256 + p) * 4096;
    float2 s = {0.0f, 0.0f};
#pragma unroll 8
    for (int i = 0; i < 64; i++) {
        float2 w = wp[i * 64 + o];
        cfma(s, Xs[b][i], w);
    }
    d_Of[(size_t)(b * 64 + o) * 8192 + kxIdx * 64 + ky] = s;
}

// ---------------- expert tiles via LoRA factorization ----------------
__global__ __launch_bounds__(512) void expert_mul_k() {
    int tile = blockIdx.x;
    int half = tile / 15, e = tile % 15;
    int p = blockIdx.y;
    int x = p >> 4, y = p & 15;
    int Rr = (e + 1) >> 2, Cc = (e + 1) & 3;
    int ky = Cc * 16 + y;
    int kxIdx = (half == 0) ? (Rr * 16 + x) : (64 + (3 - Rr) * 16 + x);
    __shared__ float2 Xs[8][64];
    __shared__ float2 Ts[8][4];
    int tid = threadIdx.x;
    {
        int b = tid >> 6, i = tid & 63;
        Xs[b][i] = d_Xf[(size_t)(b * 64 + i) * 8192 + kxIdx * 64 + ky];
    }
    __syncthreads();
    if (tid < 32) {
        int b = tid >> 2, r = tid & 3;
        const float2* lap = d_la + (size_t)(half * 15 + e) * 256 + r * 64;
        float2 s = {0.0f, 0.0f};
#pragma unroll 8
        for (int i = 0; i < 64; i++) cfma(s, Xs[b][i], lap[i]);
        Ts[b][r] = s;
    }
    __syncthreads();
    int o = tid & 63, b = tid >> 6;
    const float2* lbp = d_lbt + ((size_t)(half * 15 + e) * 256 + p) * 256;
    float2 s = {0.0f, 0.0f};
#pragma unroll
    for (int r = 0; r < 4; r++) {
        float2 w = lbp[r * 64 + o];
        cfma(s, Ts[b][r], w);
    }
    float g = d_gate[half * 15 + e] * 0.1f;
    s.x *= g; s.y *= g;
    d_Of[(size_t)(b * 64 + o) * 8192 + kxIdx * 64 + ky] = s;
}

// ---------------------------------- launch ----------------------------------
extern "C" void kernel_launch(void* const* d_in, const int* in_sizes, int n_in,
                              void* d_out, int out_size) {
    const float* x     = (const float*)d_in[0];
    const float* w1re  = (const float*)d_in[1];
    const float* w1im  = (const float*)d_in[2];
    const float* w2re  = (const float*)d_in[3];
    const float* w2im  = (const float*)d_in[4];
    const float* la1re = (const float*)d_in[5];
    const float* la1im = (const float*)d_in[6];
    const float* lb1re = (const float*)d_in[7];
    const float* lb1im = (const float*)d_in[8];
    const float* la2re = (const float*)d_in[9];
    const float* la2im = (const float*)d_in[10];
    const float* lb2re = (const float*)d_in[11];
    const float* lb2im = (const float*)d_in[12];
    const float* g1    = (const float*)d_in[13];
    const float* g2    = (const float*)d_in[14];
    float* out = (float*)d_out;

    void *pA, *pZ, *pXf, *pOf, *pFW, *pFH, *pFHI, *pFIW;
    cudaGetSymbolAddress(&pA, d_A);
    cudaGetSymbolAddress(&pZ, d_Z);
    cudaGetSymbolAddress(&pXf, d_Xf);
    cudaGetSymbolAddress(&pOf, d_Of);
    cudaGetSymbolAddress(&pFW, d_FW);
    cudaGetSymbolAddress(&pFH, d_FH);
    cudaGetSymbolAddress(&pFHI, d_FHI);
    cudaGetSymbolAddress(&pFIW, d_FIW);

    float* sp_out = (out_size > NTOT) ? (out + NTOT) : nullptr;

    init_tables_k<<<512, 256>>>();
    init_wt_k<<<8192, 256>>>(w1re, w1im, w2re, w2im);
    init_lbt_k<<<7680, 256>>>(lb1re, lb1im, lb2re, lb2im);
    init_small_k<<<1, 256>>>(la1re, la1im, la2re, la2im, g1, g2, sp_out);

    // K1: A[bc*h][2ky+c] = x[bc*h][w] * FW[w][2ky+c]
    sgemm_k<<<dim3(1024, 1), 256>>>(x, (const float*)pFW, (float*)pA, 256, 128);
    // K2: Xf[bc][kxIdx][ky] = FH[kxIdx][h] * A[bc][h][ky]
    cgemm_k<<<dim3(512, 2), 256>>>((const float2*)pFH, (const float2*)pA, (float2*)pXf, 128, 256);
    // spectral multiply
    base_mul_k<<<dim3(2, 256), 512>>>();
    expert_mul_k<<<dim3(30, 256), 512>>>();
    // K5: Z[bo][h][ky] = FHI[h][kxIdx] * Of[bo][kxIdx][ky]
    cgemm_k<<<dim3(512, 4), 256>>>((const float2*)pFHI, (const float2*)pOf, (float2*)pZ, 256, 128);
    // K6: y[bo*h][w] = Z[bo*h][2ky+c] * FIW[2ky+c][w]
    sgemm_k<<<dim3(1024, 2), 256>>>((const float*)pZ, (const float*)pFIW, out, 128, 256);
}

// round 3
// speedup vs baseline: 1.0005x; 1.0005x over previous
#include <cuda_runtime.h>
#include <math.h>

// Problem constants
// B=8, CI=CO=64, H=W=256, M1=M2=16, G=4, NEXP=15, RANK=4, SCALING=0.1
#define NTOT (8*64*256*256)

// ---------------- scratch (device globals; no allocation allowed) ----------------
__device__ float  d_FW [256*128];       // forward W-DFT matrix  [w][2*ky + re/im]
__device__ float2 d_FH [128*256];       // forward H-DFT matrix  [kxIdx][h]
__device__ float2 d_FHI[256*128];       // inverse H matrix      [h][kxIdx]
__device__ float  d_FIW[128*256];       // inverse W matrix      [2*ky+c][w]  (1/(H*W) folded)
__device__ float  d_A  [512*256*128];   // stage1 out: [bc][h][2*ky+c]
__device__ float2 d_Xf [512*128*64];    // x_ft corners [bc][kxIdx][ky]
__device__ float2 d_Of [512*128*64];    // out_ft corners [bo][kxIdx][ky]
__device__ float  d_Z  [512*256*128];   // stage5 out: [bo][h][2*ky+c]
__device__ float2 d_wt [2*256*64*64];   // transposed base weights [t][p][i][o]
__device__ float2 d_lbt[2*15*256*4*64]; // transposed lora_b [t][e][p][r][o]
__device__ float2 d_la [2*15*4*64];     // lora_a complex [t][e][r][i]
__device__ float  d_gate[30];           // sigmoid(gate) [t*15+e]

// ---------------- packed fp32x2 helpers (FFMA2 — PTX-only on sm_103a) ----------------
#define FMAX2(acc, a, b) \
    asm("fma.rn.f32x2 %0, %1, %2, %0;" : "+l"(acc) : "l"(a), "l"(b))
#define PACK2(d, x, y) \
    asm("mov.b64 %0, {%1, %2};" : "=l"(d) : "f"(x), "f"(y))

__device__ __forceinline__ void cfma(float2& c, float2 a, float2 b) {
    c.x = fmaf(a.x, b.x, c.x); c.x = fmaf(-a.y, b.y, c.x);
    c.y = fmaf(a.x, b.y, c.y); c.y = fmaf( a.y, b.x, c.y);
}

// ---------------- init: trig tables (index reduced mod 256 -> exact periodicity) ------
__global__ void init_tables_k() {
    int id = blockIdx.x * 256 + threadIdx.x;
    const float STEP = 6.283185307179586f / 256.0f;
    if (id < 32768) {                       // FW
        int w = id >> 7, n = id & 127, ky = n >> 1;
        float ang = STEP * (float)((w * ky) & 255);
        d_FW[id] = (n & 1) ? -sinf(ang) : cosf(ang);
    } else if (id < 65536) {                // FH
        int r = id - 32768; int kxi = r >> 8, h = r & 255;
        int kx = (kxi < 64) ? kxi : kxi + 128;
        float ang = STEP * (float)((kx * h) & 255);
        d_FH[r] = make_float2(cosf(ang), -sinf(ang));
    } else if (id < 98304) {                // FHI
        int r = id - 65536; int h = r >> 7, kxi = r & 127;
        int kx = (kxi < 64) ? kxi : kxi + 128;
        float ang = STEP * (float)((kx * h) & 255);
        d_FHI[r] = make_float2(cosf(ang), sinf(ang));
    } else if (id < 131072) {               // FIW (1/65536 folded, Im(ky=0) row -> sin(0)=0)
        int r = id - 98304; int n = r >> 8, w = r & 255, k = n >> 1;
        float s = ((k == 0) ? 1.0f : 2.0f) * (1.0f / 65536.0f);
        float ang = STEP * (float)((k * w) & 255);
        d_FIW[r] = (n & 1) ? -s * sinf(ang) : s * cosf(ang);
    }
}

__global__ void init_wt_k(const float* __restrict__ w1re, const float* __restrict__ w1im,
                          const float* __restrict__ w2re, const float* __restrict__ w2im) {
    int id = blockIdx.x * 256 + threadIdx.x;
    if (id >= 2 * 256 * 4096) return;
    int t = id >> 20, rem = id & 1048575;
    int p = rem >> 12, io = rem & 4095;
    int i = io >> 6, o = io & 63;
    const float* re = t ? w2re : w1re;
    const float* im = t ? w2im : w1im;
    size_t src = ((size_t)(i * 64 + o)) * 256 + p;
    d_wt[id] = make_float2(re[src], im[src]);
}

__global__ void init_lbt_k(const float* __restrict__ b1re, const float* __restrict__ b1im,
                           const float* __restrict__ b2re, const float* __restrict__ b2im) {
    int id = blockIdx.x * 256 + threadIdx.x;
    if (id >= 2 * 15 * 256 * 256) return;
    int t = id / 983040, rem = id % 983040;
    int e = rem >> 16, rem2 = rem & 65535;
    int p = rem2 >> 8, ro = rem2 & 255;
    int r = ro >> 6, o = ro & 63;
    const float* re = t ? b2re : b1re;
    const float* im = t ? b2im : b1im;
    size_t src = (((size_t)(e * 64 + o)) * 4 + r) * 256 + p;
    d_lbt[id] = make_float2(re[src], im[src]);
}

__global__ void init_small_k(const float* __restrict__ la1re, const float* __restrict__ la1im,
                             const float* __restrict__ la2re, const float* __restrict__ la2im,
                             const float* __restrict__ g1, const float* __restrict__ g2,
                             float* sp_out) {
    int tid = threadIdx.x;
    for (int id = tid; id < 7680; id += 256) {
        int t = id / 3840, rem = id % 3840;
        const float* re = t ? la2re : la1re;
        const float* im = t ? la2im : la1im;
        d_la[id] = make_float2(re[rem], im[rem]);
    }
    __shared__ float gs[30];
    if (tid < 30) {
        float v = (tid < 15) ? g1[tid] : g2[tid - 15];
        float s = 1.0f / (1.0f + expf(-v));
        d_gate[tid] = s;
        gs[tid] = s;
    }
    __syncthreads();
    if (tid == 0 && sp_out) {
        float s = 0.0f;
        for (int i = 0; i < 30; i++) s += gs[i];
        *sp_out = s / 15.0f;
    }
}

// ---------------- fp32 SGEMM, packed f32x2 inner loop ----------------
// BM=128, BN=128, BK=16, 256 threads, 8x8 micro-tile (stored as 8x4 f32x2 pairs).
__global__ __launch_bounds__(256) void sgemm_k(const float* __restrict__ Amat,
                                               const float* __restrict__ Bmat,
                                               float* __restrict__ Cmat,
                                               int Kdim, int Ncols) {
    __shared__ float As[16][128];
    __shared__ float Bs[16][128];
    int tid = threadIdx.x;
    int m0 = blockIdx.x * 128, n0 = blockIdx.y * 128;
    int tx = tid & 15, ty = tid >> 4;
    unsigned long long accp[8][4] = {};   // zero bits == {0.0f, 0.0f}
    for (int k0 = 0; k0 < Kdim; k0 += 16) {
#pragma unroll
        for (int l = 0; l < 2; l++) {
            int flat = tid + l * 256;
            int row = flat >> 2, c4 = (flat & 3) * 4;
            float4 v = *(const float4*)(Amat + (size_t)(m0 + row) * Kdim + k0 + c4);
            As[c4 + 0][row] = v.x; As[c4 + 1][row] = v.y;
            As[c4 + 2][row] = v.z; As[c4 + 3][row] = v.w;
        }
#pragma unroll
        for (int l = 0; l < 2; l++) {
            int flat = tid + l * 256;
            int row = flat >> 5, c4 = (flat & 31) * 4;
            *(float4*)(&Bs[row][c4]) = *(const float4*)(Bmat + (size_t)(k0 + row) * Ncols + n0 + c4);
        }
        __syncthreads();
#pragma unroll
        for (int k = 0; k < 16; k++) {
            float4 a0 = *(const float4*)(&As[k][ty * 4]);
            float4 a1 = *(const float4*)(&As[k][64 + ty * 4]);
            unsigned long long ap[8];
            PACK2(ap[0], a0.x, a0.x); PACK2(ap[1], a0.y, a0.y);
            PACK2(ap[2], a0.z, a0.z); PACK2(ap[3], a0.w, a0.w);
            PACK2(ap[4], a1.x, a1.x); PACK2(ap[5], a1.y, a1.y);
            PACK2(ap[6], a1.z, a1.z); PACK2(ap[7], a1.w, a1.w);
            unsigned long long bp[4];
            bp[0] = *(const unsigned long long*)(&Bs[k][tx * 4]);
            bp[1] = *(const unsigned long long*)(&Bs[k][tx * 4 + 2]);
            bp[2] = *(const unsigned long long*)(&Bs[k][64 + tx * 4]);
            bp[3] = *(const unsigned long long*)(&Bs[k][64 + tx * 4 + 2]);
#pragma unroll
            for (int i = 0; i < 8; i++)
#pragma unroll
                for (int j = 0; j < 4; j++)
                    FMAX2(accp[i][j], ap[i], bp[j]);
        }
        __syncthreads();
    }
#pragma unroll
    for (int i = 0; i < 8; i++) {
        int m = m0 + ((i < 4) ? (ty * 4 + i) : (64 + ty * 4 + (i - 4)));
        float2 p0 = *(float2*)(&accp[i][0]);
        float2 p1 = *(float2*)(&accp[i][1]);
        float2 p2 = *(float2*)(&accp[i][2]);
        float2 p3 = *(float2*)(&accp[i][3]);
        float4 v0 = {p0.x, p0.y, p1.x, p1.y};
        float4 v1 = {p2.x, p2.y, p3.x, p3.y};
        *(float4*)(Cmat + (size_t)m * Ncols + n0 + tx * 4)      = v0;
        *(float4*)(Cmat + (size_t)m * Ncols + n0 + 64 + tx * 4) = v1;
    }
}

// ---------------- batched complex GEMM, packed f32x2 inner loop ----------------
// C[bat][M,64] = F[M,K] (shared across batch) * Bm[bat][K,64]
// BM=64, BN=64, BK=16, 256 threads, 4x4 complex micro-tile.
// Complex MAC: acc{re,im} += {f.x,f.x}*{b.x,b.y} + {f.y,f.y}*{-b.y,b.x}
__global__ __launch_bounds__(256) void cgemm_k(const float2* __restrict__ F,
                                               const float2* __restrict__ Bm,
                                               float2* __restrict__ Cm,
                                               int Mdim, int Kdim) {
    int bat = blockIdx.x;
    int m0 = blockIdx.y * 64;
    const float2* Bb = Bm + (size_t)bat * Kdim * 64;
    float2* Cb = Cm + (size_t)bat * Mdim * 64;
    __shared__ float2 Fs[16][64];
    __shared__ float2 Bs[16][64];
    __shared__ float2 Bw[16][64];   // negated-swapped copy {-im, re}
    int tid = threadIdx.x;
    int tx = tid & 15, ty = tid >> 4;
    unsigned long long acc[4][4] = {};
    for (int k0 = 0; k0 < Kdim; k0 += 16) {
#pragma unroll
        for (int l = 0; l < 2; l++) {
            int flat = tid + l * 256;
            int row = flat >> 3, c = flat & 7;
            float4 v = *(const float4*)(F + (size_t)(m0 + row) * Kdim + k0 + c * 2);
            Fs[c * 2][row]     = make_float2(v.x, v.y);
            Fs[c * 2 + 1][row] = make_float2(v.z, v.w);
        }
#pragma unroll
        for (int l = 0; l < 2; l++) {
            int flat = tid + l * 256;
            int row = flat >> 5, c = flat & 31;
            float4 v = *(const float4*)(Bb + (size_t)(k0 + row) * 64 + c * 2);
            Bs[row][c * 2]     = make_float2(v.x, v.y);
            Bs[row][c * 2 + 1] = make_float2(v.z, v.w);
            Bw[row][c * 2]     = make_float2(-v.y, v.x);
            Bw[row][c * 2 + 1] = make_float2(-v.w, v.z);
        }
        __syncthreads();
#pragma unroll
        for (int k = 0; k < 16; k++) {
            float4 f01 = *(const float4*)(&Fs[k][ty * 4]);
            float4 f23 = *(const float4*)(&Fs[k][ty * 4 + 2]);
            unsigned long long fx[4], fy[4];
            PACK2(fx[0], f01.x, f01.x); PACK2(fy[0], f01.y, f01.y);
            PACK2(fx[1], f01.z, f01.z); PACK2(fy[1], f01.w, f01.w);
            PACK2(fx[2], f23.x, f23.x); PACK2(fy[2], f23.y, f23.y);
            PACK2(fx[3], f23.z, f23.z); PACK2(fy[3], f23.w, f23.w);
            unsigned long long bp[4], bw[4];
#pragma unroll
            for (int j = 0; j < 4; j++) {
                bp[j] = *(const unsigned long long*)(&Bs[k][tx * 4 + j]);
                bw[j] = *(const unsigned long long*)(&Bw[k][tx * 4 + j]);
            }
#pragma unroll
            for (int i = 0; i < 4; i++)
#pragma unroll
                for (int j = 0; j < 4; j++) {
                    FMAX2(acc[i][j], fx[i], bp[j]);
                    FMAX2(acc[i][j], fy[i], bw[j]);
                }
        }
        __syncthreads();
    }
#pragma unroll
    for (int i = 0; i < 4; i++) {
        int m = m0 + ty * 4 + i;
#pragma unroll
        for (int j = 0; j < 4; j += 2) {
            float2 p0 = *(float2*)(&acc[i][j]);
            float2 p1 = *(float2*)(&acc[i][j + 1]);
            float4 v = {p0.x, p0.y, p1.x, p1.y};
            *(float4*)(Cb + (size_t)m * 64 + tx * 4 + j) = v;
        }
    }
}

// ---------------- base tiles: Of[b,o,p] = sum_i Xf[b,i,p] * w[i,o,p] ----------------
__global__ __launch_bounds__(512) void base_mul_k() {
    int t = blockIdx.x;
    int p = blockIdx.y;
    int x = p >> 4, y = p & 15;
    int kxIdx = (t == 0) ? x : (112 + x);
    int ky = y;
    __shared__ float2 Xs[8][64];
    int tid = threadIdx.x;
    {
        int b = tid >> 6, i = tid & 63;
        Xs[b][i] = d_Xf[(size_t)(b * 64 + i) * 8192 + kxIdx * 64 + ky];
    }
    __syncthreads();
    int o = tid & 63, b = tid >> 6;
    const float2* wp = d_wt + ((size_t)t * 256 + p) * 4096;
    float2 s = {0.0f, 0.0f};
#pragma unroll 8
    for (int i = 0; i < 64; i++) {
        float2 w = wp[i * 64 + o];
        cfma(s, Xs[b][i], w);
    }
    d_Of[(size_t)(b * 64 + o) * 8192 + kxIdx * 64 + ky] = s;
}

// ---------------- expert tiles via LoRA factorization ----------------
__global__ __launch_bounds__(512) void expert_mul_k() {
    int tile = blockIdx.x;
    int half = tile / 15, e = tile % 15;
    int p = blockIdx.y;
    int x = p >> 4, y = p & 15;
    int Rr = (e + 1) >> 2, Cc = (e + 1) & 3;
    int ky = Cc * 16 + y;
    int kxIdx = (half == 0) ? (Rr * 16 + x) : (64 + (3 - Rr) * 16 + x);
    __shared__ float2 Xs[8][64];
    __shared__ float2 Ts[8][4];
    int tid = threadIdx.x;
    {
        int b = tid >> 6, i = tid & 63;
        Xs[b][i] = d_Xf[(size_t)(b * 64 + i) * 8192 + kxIdx * 64 + ky];
    }
    __syncthreads();
    if (tid < 32) {
        int b = tid >> 2, r = tid & 3;
        const float2* lap = d_la + (size_t)(half * 15 + e) * 256 + r * 64;
        float2 s = {0.0f, 0.0f};
#pragma unroll 8
        for (int i = 0; i < 64; i++) cfma(s, Xs[b][i], lap[i]);
        Ts[b][r] = s;
    }
    __syncthreads();
    int o = tid & 63, b = tid >> 6;
    const float2* lbp = d_lbt + ((size_t)(half * 15 + e) * 256 + p) * 256;
    float2 s = {0.0f, 0.0f};
#pragma unroll
    for (int r = 0; r < 4; r++) {
        float2 w = lbp[r * 64 + o];
        cfma(s, Ts[b][r], w);
    }
    float g = d_gate[half * 15 + e] * 0.1f;
    s.x *= g; s.y *= g;
    d_Of[(size_t)(b * 64 + o) * 8192 + kxIdx * 64 + ky] = s;
}

// ---------------------------------- launch ----------------------------------
extern "C" void kernel_launch(void* const* d_in, const int* in_sizes, int n_in,
                              void* d_out, int out_size) {
    const float* x     = (const float*)d_in[0];
    const float* w1re  = (const float*)d_in[1];
    const float* w1im  = (const float*)d_in[2];
    const float* w2re  = (const float*)d_in[3];
    const float* w2im  = (const float*)d_in[4];
    const float* la1re = (const float*)d_in[5];
    const float* la1im = (const float*)d_in[6];
    const float* lb1re = (const float*)d_in[7];
    const float* lb1im = (const float*)d_in[8];
    const float* la2re = (const float*)d_in[9];
    const float* la2im = (const float*)d_in[10];
    const float* lb2re = (const float*)d_in[11];
    const float* lb2im = (const float*)d_in[12];
    const float* g1    = (const float*)d_in[13];
    const float* g2    = (const float*)d_in[14];
    float* out = (float*)d_out;

    void *pA, *pZ, *pXf, *pOf, *pFW, *pFH, *pFHI, *pFIW;
    cudaGetSymbolAddress(&pA, d_A);
    cudaGetSymbolAddress(&pZ, d_Z);
    cudaGetSymbolAddress(&pXf, d_Xf);
    cudaGetSymbolAddress(&pOf, d_Of);
    cudaGetSymbolAddress(&pFW, d_FW);
    cudaGetSymbolAddress(&pFH, d_FH);
    cudaGetSymbolAddress(&pFHI, d_FHI);
    cudaGetSymbolAddress(&pFIW, d_FIW);

    float* sp_out = (out_size > NTOT) ? (out + NTOT) : nullptr;

    init_tables_k<<<512, 256>>>();
    init_wt_k<<<8192, 256>>>(w1re, w1im, w2re, w2im);
    init_lbt_k<<<7680, 256>>>(lb1re, lb1im, lb2re, lb2im);
    init_small_k<<<1, 256>>>(la1re, la1im, la2re, la2im, g1, g2, sp_out);

    // K1: A[bc*h][2ky+c] = x[bc*h][w] * FW[w][2ky+c]
    sgemm_k<<<dim3(1024, 1), 256>>>(x, (const float*)pFW, (float*)pA, 256, 128);
    // K2: Xf[bc][kxIdx][ky] = FH[kxIdx][h] * A[bc][h][ky]
    cgemm_k<<<dim3(512, 2), 256>>>((const float2*)pFH, (const float2*)pA, (float2*)pXf, 128, 256);
    // spectral multiply
    base_mul_k<<<dim3(2, 256), 512>>>();
    expert_mul_k<<<dim3(30, 256), 512>>>();
    // K5: Z[bo][h][ky] = FHI[h][kxIdx] * Of[bo][kxIdx][ky]
    cgemm_k<<<dim3(512, 4), 256>>>((const float2*)pFHI, (const float2*)pOf, (float2*)pZ, 256, 128);
    // K6: y[bo*h][w] = Z[bo*h][2ky+c] * FIW[2ky+c][w]
    sgemm_k<<<dim3(1024, 2), 256>>>((const float*)pZ, (const float*)pFIW, out, 128, 256);
}